// round 2
// baseline (speedup 1.0000x reference)
#include <cuda_runtime.h>
#include <cuda_bf16.h>

// Problem constants (fixed by the reference setup)
#define B_   4
#define C_   256
#define H_   200
#define W_   304
#define OUT_ 7
#define NBIN 49            // OUT_*OUT_
#define CN   (C_ * NBIN)   // 12544 outputs per roi
#define SCALE_ 0.25f

__global__ __launch_bounds__(256, 8)
void roi_align_kernel(const float* __restrict__ feat,
                      const float* __restrict__ rois,
                      float* __restrict__ out)
{
    const int n   = blockIdx.x;
    const int tid = threadIdx.x;

    __shared__ int   s_off0[NBIN], s_off1[NBIN], s_off2[NBIN], s_off3[NBIN];
    __shared__ float s_w0[NBIN], s_w1[NBIN], s_w2[NBIN], s_w3[NBIN];
    __shared__ int   s_b;

    if (tid < NBIN) {
        const float rx1 = rois[n * 5 + 1] * SCALE_;
        const float ry1 = rois[n * 5 + 2] * SCALE_;
        const float rx2 = rois[n * 5 + 3] * SCALE_;
        const float ry2 = rois[n * 5 + 4] * SCALE_;
        const float rw = fmaxf(rx2 - rx1, 1.0f);
        const float rh = fmaxf(ry2 - ry1, 1.0f);
        const float bw = rw * (1.0f / OUT_);
        const float bh = rh * (1.0f / OUT_);

        const int oy = tid / OUT_;
        const int ox = tid - oy * OUT_;

        float y = ry1 + ((float)oy + 0.5f) * bh;
        float x = rx1 + ((float)ox + 0.5f) * bw;

        const bool valid = (y > -1.0f) && (y < (float)H_) &&
                           (x > -1.0f) && (x < (float)W_);

        y = fminf(fmaxf(y, 0.0f), (float)(H_ - 1));
        x = fminf(fmaxf(x, 0.0f), (float)(W_ - 1));

        int y0 = (int)floorf(y);
        int x0 = (int)floorf(x);
        int y1 = min(y0 + 1, H_ - 1);
        int x1 = min(x0 + 1, W_ - 1);

        const float ly = y - (float)y0;
        const float lx = x - (float)x0;
        const float hy = 1.0f - ly;
        const float hx = 1.0f - lx;
        const float v  = valid ? 1.0f : 0.0f;

        // Precompute flat in-plane offsets for the 4 bilinear corners.
        s_off0[tid] = y0 * W_ + x0;
        s_off1[tid] = y0 * W_ + x1;
        s_off2[tid] = y1 * W_ + x0;
        s_off3[tid] = y1 * W_ + x1;
        s_w0[tid] = hy * hx * v;
        s_w1[tid] = hy * lx * v;
        s_w2[tid] = ly * hx * v;
        s_w3[tid] = ly * lx * v;
    }
    if (tid == 0) s_b = (int)rois[n * 5 + 0];
    __syncthreads();

    const float* __restrict__ fb = feat + (size_t)s_b * (C_ * H_ * W_);
    float* __restrict__ obase = out + (size_t)n * CN;

    // Flattened mapping: k = c*49 + i. Stores are fully coalesced.
    #pragma unroll 7
    for (int k = tid; k < CN; k += 256) {
        const unsigned c = (unsigned)k / NBIN;          // mul-shift
        const int      i = k - (int)c * NBIN;
        const float* __restrict__ plane = fb + (size_t)c * (H_ * W_);
        const float v = plane[s_off0[i]] * s_w0[i]
                      + plane[s_off1[i]] * s_w1[i]
                      + plane[s_off2[i]] * s_w2[i]
                      + plane[s_off3[i]] * s_w3[i];
        obase[k] = v;
    }
}

extern "C" void kernel_launch(void* const* d_in, const int* in_sizes, int n_in,
                              void* d_out, int out_size)
{
    const float* feat = (const float*)d_in[0];
    const float* rois = (const float*)d_in[1];
    float* out        = (float*)d_out;

    const int N = in_sizes[1] / 5;   // 2000 rois
    roi_align_kernel<<<N, 256>>>(feat, rois, out);
}

// round 5
// speedup vs baseline: 1.1090x; 1.1090x over previous
#include <cuda_runtime.h>
#include <cuda_bf16.h>

// Problem constants (fixed by the reference setup)
#define B_    4
#define C_    256
#define H_    200
#define W_    304
#define HW_   (H_ * W_)
#define OUT_  7
#define NBIN  49               // OUT_*OUT_
#define CPHASE 8               // channel phases per block
#define NTHREADS (NBIN * CPHASE)   // 392
#define NITER (C_ / CPHASE)    // 32 channels per thread
#define SCALE_ 0.25f

__global__ __launch_bounds__(NTHREADS)
void roi_align_kernel(const float* __restrict__ feat,
                      const float* __restrict__ rois,
                      float* __restrict__ out)
{
    const int n   = blockIdx.x;
    const int tid = threadIdx.x;
    const int i   = tid % NBIN;   // bin id (mul-shift, once)
    const int c0  = tid / NBIN;   // channel phase 0..7

    // ---- per-thread bin constants (registers) ----
    const float rb  = __ldg(&rois[n * 5 + 0]);
    const float rx1 = __ldg(&rois[n * 5 + 1]) * SCALE_;
    const float ry1 = __ldg(&rois[n * 5 + 2]) * SCALE_;
    const float rx2 = __ldg(&rois[n * 5 + 3]) * SCALE_;
    const float ry2 = __ldg(&rois[n * 5 + 4]) * SCALE_;

    const float rw = fmaxf(rx2 - rx1, 1.0f);
    const float rh = fmaxf(ry2 - ry1, 1.0f);
    const float bw = rw * (1.0f / OUT_);
    const float bh = rh * (1.0f / OUT_);

    const int oy = i / OUT_;
    const int ox = i - oy * OUT_;

    float y = ry1 + ((float)oy + 0.5f) * bh;
    float x = rx1 + ((float)ox + 0.5f) * bw;

    const bool valid = (y > -1.0f) && (y < (float)H_) &&
                       (x > -1.0f) && (x < (float)W_);

    y = fminf(fmaxf(y, 0.0f), (float)(H_ - 1));
    x = fminf(fmaxf(x, 0.0f), (float)(W_ - 1));

    int y0 = (int)floorf(y);
    int x0 = (int)floorf(x);
    int y1 = min(y0 + 1, H_ - 1);
    int x1 = min(x0 + 1, W_ - 1);

    const float ly = y - (float)y0;
    const float lx = x - (float)x0;
    const float hy = 1.0f - ly;
    const float hx = 1.0f - lx;
    const float vf = valid ? 1.0f : 0.0f;

    const float w0 = hy * hx * vf;   // (y0, x0)
    const float w1 = hy * lx * vf;   // (y0, x1)
    const float w2 = ly * hx * vf;   // (y1, x0)
    const float w3 = ly * lx * vf;   // (y1, x1)

    const int off0 = y0 * W_ + x0;
    const int off1 = y0 * W_ + x1;
    const int off2 = y1 * W_ + x0;
    const int off3 = y1 * W_ + x1;

    // ---- main loop: 32 channels per thread ----
    const int b = (int)rb;
    const float* __restrict__ plane =
        feat + (size_t)b * (C_ * HW_) + (size_t)c0 * HW_;
    float* __restrict__ optr = out + (size_t)n * (C_ * NBIN) + tid;

    #pragma unroll 4
    for (int j = 0; j < NITER; ++j) {
        // Row-paired loads: (off0,off1) share a row (usually same/adjacent
        // sector), likewise (off2,off3) — batches L1 wavefronts.
        const float a0 = plane[off0];
        const float a1 = plane[off1];
        const float a2 = plane[off2];
        const float a3 = plane[off3];
        const float vtop = a0 * w0 + a1 * w1;
        const float vbot = a2 * w2 + a3 * w3;
        *optr = vtop + vbot;
        plane += CPHASE * HW_;   // next channel for this phase
        optr  += NTHREADS;       // coalesced store stride
    }
}

extern "C" void kernel_launch(void* const* d_in, const int* in_sizes, int n_in,
                              void* d_out, int out_size)
{
    const float* feat = (const float*)d_in[0];
    const float* rois = (const float*)d_in[1];
    float* out        = (float*)d_out;

    const int N = in_sizes[1] / 5;   // 2000 rois
    roi_align_kernel<<<N, NTHREADS>>>(feat, rois, out);
}